// round 1
// baseline (speedup 1.0000x reference)
#include <cuda_runtime.h>
#include <cuda_bf16.h>
#include <math.h>

// Problem constants
#define T_STEPS 128
#define BATCH   256
#define V_DIM   256
#define N_DIM   1024
#define TB      (T_STEPS * BATCH)          // 32768
#define SLAB    (BATCH * N_DIM)            // 262144 floats per time slab
#define NSPLIT  4                          // split-K factor for recurrent GEMM

// Scratch (device globals: no allocations allowed)
__device__ float g_seq[(size_t)T_STEPS * SLAB];   // 128 MB: xw pre-activations, then h_t in place
__device__ float g_part[(size_t)NSPLIT * SLAB];   // 4 MB: split-K partials
__device__ float g_logits[(size_t)TB * V_DIM];    // 33.5 MB
__device__ float g_rowloss[TB];

// ---------------------------------------------------------------------------
// Tiled SGEMM: C[M,N] = A[M,K] @ B[K,N]  (row-major, all dims multiples of 64/16)
// BM=BN=64, BK=16, 256 threads, 4x4 micro-tile.
// MODE 0: C = acc + bias[col]          (gridDim.z == 1, kChunk == K)
// MODE 1: C + z*partStride = acc       (split-K partials, k0 = z*kChunk)
// ---------------------------------------------------------------------------
template <int MODE>
__global__ void __launch_bounds__(256, 2)
sgemm_tile(const float* __restrict__ A, const float* __restrict__ B,
           float* __restrict__ C, const float* __restrict__ bias,
           int lda, int ldb, int ldc, int kChunk, int partStride)
{
    __shared__ float As[16][64];   // transposed A tile: As[k][m]
    __shared__ float Bs[16][64];   // Bs[k][n]

    const int tid = threadIdx.x;
    const int row0 = blockIdx.y * 64;
    const int col0 = blockIdx.x * 64;
    const int k0 = blockIdx.z * kChunk;

    float* Cout = C;
    if (MODE == 1) Cout += (size_t)blockIdx.z * partStride;

    // A tile loader: thread -> (row ar, 4 cols at ac4)
    const int ar  = tid >> 2;
    const int ac4 = (tid & 3) * 4;
    // B tile loader: thread -> (row br, 4 cols at bc4)
    const int br  = tid >> 4;
    const int bc4 = (tid & 15) * 4;

    const int ty = tid >> 4;   // 0..15 (m)
    const int tx = tid & 15;   // 0..15 (n)

    float acc[4][4] = {};

    for (int kt = 0; kt < kChunk; kt += 16) {
        float4 av = *(const float4*)(A + (size_t)(row0 + ar) * lda + (k0 + kt + ac4));
        As[ac4 + 0][ar] = av.x;
        As[ac4 + 1][ar] = av.y;
        As[ac4 + 2][ar] = av.z;
        As[ac4 + 3][ar] = av.w;
        *(float4*)&Bs[br][bc4] =
            *(const float4*)(B + (size_t)(k0 + kt + br) * ldb + (col0 + bc4));
        __syncthreads();

#pragma unroll
        for (int k = 0; k < 16; k++) {
            float4 a4 = *(const float4*)&As[k][ty * 4];
            float4 b4 = *(const float4*)&Bs[k][tx * 4];
            float a[4] = {a4.x, a4.y, a4.z, a4.w};
            float b[4] = {b4.x, b4.y, b4.z, b4.w};
#pragma unroll
            for (int i = 0; i < 4; i++)
#pragma unroll
                for (int j = 0; j < 4; j++)
                    acc[i][j] = fmaf(a[i], b[j], acc[i][j]);
        }
        __syncthreads();
    }

#pragma unroll
    for (int i = 0; i < 4; i++) {
        int r = row0 + ty * 4 + i;
#pragma unroll
        for (int j = 0; j < 4; j++) {
            int c = col0 + tx * 4 + j;
            float v = acc[i][j];
            if (MODE == 0) v += bias[c];
            Cout[(size_t)r * ldc + c] = v;
        }
    }
}

// h_0 = tanh(xw_0)  — elementwise over one slab (float4 per thread)
__global__ void tanh_slab(float* __restrict__ x)
{
    size_t i = ((size_t)blockIdx.x * blockDim.x + threadIdx.x) * 4;
    float4 v = *(float4*)(x + i);
    v.x = tanhf(v.x); v.y = tanhf(v.y); v.z = tanhf(v.z); v.w = tanhf(v.w);
    *(float4*)(x + i) = v;
}

// h_t = tanh(pre_t + sum_c partial_c)   (pre stored at h location, in place)
__global__ void step_reduce(const float* __restrict__ part, float* __restrict__ h)
{
    size_t i = ((size_t)blockIdx.x * blockDim.x + threadIdx.x) * 4;
    float4 a = *(float4*)(h + i);
#pragma unroll
    for (int c = 0; c < NSPLIT; c++) {
        float4 p = *(const float4*)(part + (size_t)c * SLAB + i);
        a.x += p.x; a.y += p.y; a.z += p.z; a.w += p.w;
    }
    a.x = tanhf(a.x); a.y = tanhf(a.y); a.z = tanhf(a.z); a.w = tanhf(a.w);
    *(float4*)(h + i) = a;
}

// Per-row soft-label cross-entropy from raw logits.
// rowloss = (max + log(sum exp(logit-max))) * sum(lab) - sum(lab*logit)
__global__ void loss_rows(const float* __restrict__ logits,
                          const float* __restrict__ labels,
                          float* __restrict__ rowloss)
{
    const int row = blockIdx.x;
    const int v = threadIdx.x;
    __shared__ float s[256];

    size_t base = (size_t)row * V_DIM;
    float logit = logits[base + v];
    float lab   = labels[base + v];

    // max
    s[v] = logit; __syncthreads();
    for (int o = 128; o > 0; o >>= 1) {
        if (v < o) s[v] = fmaxf(s[v], s[v + o]);
        __syncthreads();
    }
    float mx = s[0]; __syncthreads();

    // sum exp
    s[v] = expf(logit - mx); __syncthreads();
    for (int o = 128; o > 0; o >>= 1) {
        if (v < o) s[v] += s[v + o];
        __syncthreads();
    }
    float Z = s[0]; __syncthreads();

    // sum labels
    s[v] = lab; __syncthreads();
    for (int o = 128; o > 0; o >>= 1) {
        if (v < o) s[v] += s[v + o];
        __syncthreads();
    }
    float sumLab = s[0]; __syncthreads();

    // sum labels*logits
    s[v] = lab * logit; __syncthreads();
    for (int o = 128; o > 0; o >>= 1) {
        if (v < o) s[v] += s[v + o];
        __syncthreads();
    }
    float sumLL = s[0];

    if (v == 0)
        rowloss[row] = (mx + logf(Z)) * sumLab - sumLL;
}

// Deterministic final mean over 32768 row losses.
__global__ void final_reduce(const float* __restrict__ rowloss, float* __restrict__ out)
{
    const int v = threadIdx.x;   // 256 threads
    __shared__ float s[256];
    float acc = 0.0f;
    for (int i = v; i < TB; i += 256) acc += rowloss[i];
    s[v] = acc; __syncthreads();
    for (int o = 128; o > 0; o >>= 1) {
        if (v < o) s[v] += s[v + o];
        __syncthreads();
    }
    if (v == 0) out[0] = s[0] * (1.0f / (float)TB);
}

extern "C" void kernel_launch(void* const* d_in, const int* in_sizes, int n_in,
                              void* d_out, int out_size)
{
    const float* inputs  = (const float*)d_in[0];   // (T, B, V)
    const float* labels  = (const float*)d_in[1];   // (T*B, V)
    const float* weights = (const float*)d_in[2];   // (V+N, N)
    const float* bias    = (const float*)d_in[3];   // (N,)
    const float* ow      = (const float*)d_in[4];   // (N, V)
    const float* ob      = (const float*)d_in[5];   // (V,)
    float* out = (float*)d_out;

    float *seq, *part, *logits, *rowloss;
    cudaGetSymbolAddress((void**)&seq, g_seq);
    cudaGetSymbolAddress((void**)&part, g_part);
    cudaGetSymbolAddress((void**)&logits, g_logits);
    cudaGetSymbolAddress((void**)&rowloss, g_rowloss);

    const float* wx = weights;                         // rows [0, V)
    const float* wh = weights + (size_t)V_DIM * N_DIM; // rows [V, V+N)

    // 1) pre[t,b,n] = X @ Wx + bias  (full sequence, one big GEMM)
    sgemm_tile<0><<<dim3(N_DIM / 64, TB / 64, 1), 256>>>(
        inputs, wx, seq, bias, V_DIM, N_DIM, N_DIM, V_DIM, 0);

    // 2) h_0 = tanh(pre_0)
    tanh_slab<<<SLAB / (256 * 4), 256>>>(seq);

    // 3) recurrence: h_t = tanh(pre_t + h_{t-1} @ Wh), split-K 4-way
    for (int t = 1; t < T_STEPS; t++) {
        sgemm_tile<1><<<dim3(N_DIM / 64, BATCH / 64, NSPLIT), 256>>>(
            seq + (size_t)(t - 1) * SLAB, wh, part, nullptr,
            N_DIM, N_DIM, N_DIM, N_DIM / NSPLIT, SLAB);
        step_reduce<<<SLAB / (256 * 4), 256>>>(part, seq + (size_t)t * SLAB);
    }

    // 4) logits = H @ Wo + ob
    sgemm_tile<0><<<dim3(V_DIM / 64, TB / 64, 1), 256>>>(
        seq, ow, logits, ob, N_DIM, V_DIM, V_DIM, N_DIM, 0);

    // 5) per-row loss, then deterministic mean
    loss_rows<<<TB, 256>>>(logits, labels, rowloss);
    final_reduce<<<1, 256>>>(rowloss, out);
}

// round 3
// speedup vs baseline: 2.1429x; 2.1429x over previous
#include <cuda_runtime.h>
#include <cuda_bf16.h>
#include <math.h>
#include <stdint.h>

// Problem constants
#define T_STEPS 128
#define BATCH   256
#define V_DIM   256
#define N_DIM   1024
#define TB      (T_STEPS * BATCH)          // 32768
#define SLAB    (BATCH * N_DIM)            // 262144 floats per time slab
#define NSPLIT  8                          // split-K factor for recurrent GEMM

// Scratch (device globals: no allocations allowed)
__device__ float g_seq[(size_t)T_STEPS * SLAB];   // 128 MB: xw pre-activations, then h_t in place
__device__ float g_part[(size_t)NSPLIT * SLAB];   // 8 MB: split-K partials
__device__ float g_logits[(size_t)TB * V_DIM];    // 33.5 MB
__device__ float g_rowloss[TB];

__device__ __forceinline__ uint32_t f2tf32(float x) {
    uint32_t r;
    asm("cvt.rna.tf32.f32 %0, %1;" : "=r"(r) : "f"(x));
    return r;
}

__device__ __forceinline__ void mma_tf32(float c[4], uint32_t a0, uint32_t a1,
                                         uint32_t a2, uint32_t a3,
                                         uint32_t b0, uint32_t b1) {
    asm volatile(
        "mma.sync.aligned.m16n8k8.row.col.f32.tf32.tf32.f32 "
        "{%0,%1,%2,%3}, {%4,%5,%6,%7}, {%8,%9}, {%0,%1,%2,%3};"
        : "+f"(c[0]), "+f"(c[1]), "+f"(c[2]), "+f"(c[3])
        : "r"(a0), "r"(a1), "r"(a2), "r"(a3), "r"(b0), "r"(b1));
}

// ---------------------------------------------------------------------------
// tf32 tensor-core GEMM: C[M,N] = A[M,K] @ B[K,N]  (row-major fp32 in gmem)
// Block tile 64x64, 128 threads = 4 warps (2x2), each warp 32x32 via
// m16n8k8 tf32 mma. BK=16 per iteration.
// MODE 0: C = acc + bias[col]          (gridDim.z == 1, kChunk == K)
// MODE 1: C + z*partStride = acc       (split-K partials, k0 = z*kChunk)
// ---------------------------------------------------------------------------
#define AS_STRIDE 20   // words; conflict-free A-fragment LDS
#define BS_STRIDE 72   // words; conflict-free B-fragment LDS

template <int MODE>
__global__ void __launch_bounds__(128)
mma_gemm(const float* __restrict__ A, const float* __restrict__ B,
         float* __restrict__ C, const float* __restrict__ bias,
         int lda, int ldb, int ldc, int kChunk, int partStride)
{
    __shared__ uint32_t As[64 * AS_STRIDE];   // [m][k] tf32 bits, 64x16 tile
    __shared__ uint32_t Bs[16 * BS_STRIDE];   // [k][n] tf32 bits, 16x64 tile

    const int tid  = threadIdx.x;
    const int warp = tid >> 5;
    const int lane = tid & 31;
    const int gid  = lane >> 2;   // group id 0..7
    const int tg   = lane & 3;    // thread-in-group 0..3

    const int wm = (warp >> 1) * 32;   // warp m offset within block
    const int wn = (warp & 1) * 32;    // warp n offset

    const int row0 = blockIdx.y * 64;
    const int col0 = blockIdx.x * 64;
    const int k0   = blockIdx.z * kChunk;

    float* Cout = C;
    if (MODE == 1) Cout += (size_t)blockIdx.z * partStride;

    // A loader: 64x16 tile = 256 float4; thread handles float4 ids tid, tid+128
    const int a_r0 = tid >> 2;            // rows tid>>2 and tid>>2 + 32
    const int a_c4 = (tid & 3) * 4;
    // B loader: 16x64 tile = 256 float4; thread handles float4 ids tid, tid+128
    const int b_r0 = tid >> 4;            // rows tid>>4 and tid>>4 + 8
    const int b_c4 = (tid & 15) * 4;

    float acc[2][4][4] = {};

    for (int kt = 0; kt < kChunk; kt += 16) {
        // --- stage tiles (convert to tf32 at store time) ---
#pragma unroll
        for (int h = 0; h < 2; h++) {
            int ar = a_r0 + h * 32;
            float4 av = *(const float4*)(A + (size_t)(row0 + ar) * lda + (k0 + kt + a_c4));
            uint32_t* dst = &As[ar * AS_STRIDE + a_c4];
            dst[0] = f2tf32(av.x); dst[1] = f2tf32(av.y);
            dst[2] = f2tf32(av.z); dst[3] = f2tf32(av.w);
        }
#pragma unroll
        for (int h = 0; h < 2; h++) {
            int br = b_r0 + h * 8;
            float4 bv = *(const float4*)(B + (size_t)(k0 + kt + br) * ldb + (col0 + b_c4));
            uint32_t* dst = &Bs[br * BS_STRIDE + b_c4];
            dst[0] = f2tf32(bv.x); dst[1] = f2tf32(bv.y);
            dst[2] = f2tf32(bv.z); dst[3] = f2tf32(bv.w);
        }
        __syncthreads();

        // --- two k8 sub-steps of mma ---
#pragma unroll
        for (int ks = 0; ks < 2; ks++) {
            const int kk = ks * 8;
            uint32_t afrag[2][4];
#pragma unroll
            for (int mi = 0; mi < 2; mi++) {
                int r = wm + mi * 16 + gid;
                afrag[mi][0] = As[(r    ) * AS_STRIDE + kk + tg    ];
                afrag[mi][1] = As[(r + 8) * AS_STRIDE + kk + tg    ];
                afrag[mi][2] = As[(r    ) * AS_STRIDE + kk + tg + 4];
                afrag[mi][3] = As[(r + 8) * AS_STRIDE + kk + tg + 4];
            }
#pragma unroll
            for (int ni = 0; ni < 4; ni++) {
                int c = wn + ni * 8 + gid;
                uint32_t b0 = Bs[(kk + tg    ) * BS_STRIDE + c];
                uint32_t b1 = Bs[(kk + tg + 4) * BS_STRIDE + c];
#pragma unroll
                for (int mi = 0; mi < 2; mi++)
                    mma_tf32(acc[mi][ni], afrag[mi][0], afrag[mi][1],
                             afrag[mi][2], afrag[mi][3], b0, b1);
            }
        }
        __syncthreads();
    }

    // --- epilogue ---
#pragma unroll
    for (int mi = 0; mi < 2; mi++) {
        int r0 = row0 + wm + mi * 16 + gid;
#pragma unroll
        for (int ni = 0; ni < 4; ni++) {
            int c = col0 + wn + ni * 8 + tg * 2;
            float2 v0 = make_float2(acc[mi][ni][0], acc[mi][ni][1]);
            float2 v1 = make_float2(acc[mi][ni][2], acc[mi][ni][3]);
            if (MODE == 0) {
                float b0 = bias[c], b1 = bias[c + 1];
                v0.x += b0; v0.y += b1;
                v1.x += b0; v1.y += b1;
            }
            *(float2*)(Cout + (size_t)r0 * ldc + c)       = v0;
            *(float2*)(Cout + (size_t)(r0 + 8) * ldc + c) = v1;
        }
    }
}

// h_0 = tanh(xw_0)  — elementwise over one slab (float4 per thread)
__global__ void tanh_slab(float* __restrict__ x)
{
    size_t i = ((size_t)blockIdx.x * blockDim.x + threadIdx.x) * 4;
    float4 v = *(float4*)(x + i);
    v.x = tanhf(v.x); v.y = tanhf(v.y); v.z = tanhf(v.z); v.w = tanhf(v.w);
    *(float4*)(x + i) = v;
}

// h_t = tanh(pre_t + sum_c partial_c)   (pre stored at h location, in place)
__global__ void step_reduce(const float* __restrict__ part, float* __restrict__ h)
{
    size_t i = ((size_t)blockIdx.x * blockDim.x + threadIdx.x) * 4;
    float4 a = *(float4*)(h + i);
#pragma unroll
    for (int c = 0; c < NSPLIT; c++) {
        float4 p = *(const float4*)(part + (size_t)c * SLAB + i);
        a.x += p.x; a.y += p.y; a.z += p.z; a.w += p.w;
    }
    a.x = tanhf(a.x); a.y = tanhf(a.y); a.z = tanhf(a.z); a.w = tanhf(a.w);
    *(float4*)(h + i) = a;
}

// Per-row soft-label cross-entropy from raw logits.
// rowloss = (max + log(sum exp(logit-max))) * sum(lab) - sum(lab*logit)
__global__ void loss_rows(const float* __restrict__ logits,
                          const float* __restrict__ labels,
                          float* __restrict__ rowloss)
{
    const int row = blockIdx.x;
    const int v = threadIdx.x;
    __shared__ float s[256];

    size_t base = (size_t)row * V_DIM;
    float logit = logits[base + v];
    float lab   = labels[base + v];

    s[v] = logit; __syncthreads();
    for (int o = 128; o > 0; o >>= 1) {
        if (v < o) s[v] = fmaxf(s[v], s[v + o]);
        __syncthreads();
    }
    float mx = s[0]; __syncthreads();

    s[v] = expf(logit - mx); __syncthreads();
    for (int o = 128; o > 0; o >>= 1) {
        if (v < o) s[v] += s[v + o];
        __syncthreads();
    }
    float Z = s[0]; __syncthreads();

    s[v] = lab; __syncthreads();
    for (int o = 128; o > 0; o >>= 1) {
        if (v < o) s[v] += s[v + o];
        __syncthreads();
    }
    float sumLab = s[0]; __syncthreads();

    s[v] = lab * logit; __syncthreads();
    for (int o = 128; o > 0; o >>= 1) {
        if (v < o) s[v] += s[v + o];
        __syncthreads();
    }
    float sumLL = s[0];

    if (v == 0)
        rowloss[row] = (mx + logf(Z)) * sumLab - sumLL;
}

// Deterministic final mean over 32768 row losses.
__global__ void final_reduce(const float* __restrict__ rowloss, float* __restrict__ out)
{
    const int v = threadIdx.x;   // 256 threads
    __shared__ float s[256];
    float acc = 0.0f;
    for (int i = v; i < TB; i += 256) acc += rowloss[i];
    s[v] = acc; __syncthreads();
    for (int o = 128; o > 0; o >>= 1) {
        if (v < o) s[v] += s[v + o];
        __syncthreads();
    }
    if (v == 0) out[0] = s[0] * (1.0f / (float)TB);
}

extern "C" void kernel_launch(void* const* d_in, const int* in_sizes, int n_in,
                              void* d_out, int out_size)
{
    const float* inputs  = (const float*)d_in[0];   // (T, B, V)
    const float* labels  = (const float*)d_in[1];   // (T*B, V)
    const float* weights = (const float*)d_in[2];   // (V+N, N)
    const float* bias    = (const float*)d_in[3];   // (N,)
    const float* ow      = (const float*)d_in[4];   // (N, V)
    const float* ob      = (const float*)d_in[5];   // (V,)
    float* out = (float*)d_out;

    float *seq, *part, *logits, *rowloss;
    cudaGetSymbolAddress((void**)&seq, g_seq);
    cudaGetSymbolAddress((void**)&part, g_part);
    cudaGetSymbolAddress((void**)&logits, g_logits);
    cudaGetSymbolAddress((void**)&rowloss, g_rowloss);

    const float* wx = weights;                         // rows [0, V)
    const float* wh = weights + (size_t)V_DIM * N_DIM; // rows [V, V+N)

    // 1) pre[t,b,n] = X @ Wx + bias  (full sequence, one big GEMM)
    mma_gemm<0><<<dim3(N_DIM / 64, TB / 64, 1), 128>>>(
        inputs, wx, seq, bias, V_DIM, N_DIM, N_DIM, V_DIM, 0);

    // 2) h_0 = tanh(pre_0)
    tanh_slab<<<SLAB / (256 * 4), 256>>>(seq);

    // 3) recurrence: h_t = tanh(pre_t + h_{t-1} @ Wh), split-K 8-way
    for (int t = 1; t < T_STEPS; t++) {
        mma_gemm<1><<<dim3(N_DIM / 64, BATCH / 64, NSPLIT), 128>>>(
            seq + (size_t)(t - 1) * SLAB, wh, part, nullptr,
            N_DIM, N_DIM, N_DIM, N_DIM / NSPLIT, SLAB);
        step_reduce<<<SLAB / (256 * 4), 256>>>(part, seq + (size_t)t * SLAB);
    }

    // 4) logits = H @ Wo + ob
    mma_gemm<0><<<dim3(V_DIM / 64, TB / 64, 1), 128>>>(
        seq, ow, logits, ob, N_DIM, V_DIM, V_DIM, N_DIM, 0);

    // 5) per-row loss, then deterministic mean
    loss_rows<<<TB, 256>>>(logits, labels, rowloss);
    final_reduce<<<1, 256>>>(rowloss, out);
}